// round 5
// baseline (speedup 1.0000x reference)
#include <cuda_runtime.h>
#include <math.h>
#include <stdint.h>

#define L_SEQ  4096
#define DMODEL 1024
#define NHEADS 16
#define HDIM   64

typedef unsigned long long ull;

// Scratch (allocation-free rule: __device__ globals)
__device__ float g_q[NHEADS * L_SEQ * HDIM];
__device__ float g_k[NHEADS * L_SEQ * HDIM];
__device__ float g_v[NHEADS * L_SEQ * HDIM];
__device__ float g_attn[L_SEQ * DMODEL];
__device__ float g_wt[4 * DMODEL * DMODEL];  // transposed tf32-rounded weights [N][K]
__device__ float g_xr[L_SEQ * DMODEL];       // tf32-rounded x

// ---- packed fp32x2 helpers (attention kernel) ----
__device__ __forceinline__ ull pk2(float x, float y) {
    ull r; asm("mov.b64 %0, {%1, %2};" : "=l"(r) : "f"(x), "f"(y)); return r;
}
__device__ __forceinline__ float2 upk2(ull v) {
    float2 r; asm("mov.b64 {%0, %1}, %2;" : "=f"(r.x), "=f"(r.y) : "l"(v)); return r;
}
__device__ __forceinline__ ull ffma2(ull a, ull b, ull c) {
    ull d; asm("fma.rn.f32x2 %0, %1, %2, %3;" : "=l"(d) : "l"(a), "l"(b), "l"(c)); return d;
}
__device__ __forceinline__ ull fmul2(ull a, ull b) {
    ull d; asm("mul.rn.f32x2 %0, %1, %2;" : "=l"(d) : "l"(a), "l"(b)); return d;
}
union F4U2 { float4 f; ull u[2]; };

__device__ __forceinline__ uint32_t smem_u32(const void* p) {
    uint32_t a;
    asm("{ .reg .u64 t; cvta.to.shared.u64 t, %1; cvt.u32.u64 %0, t; }" : "=r"(a) : "l"(p));
    return a;
}
__device__ __forceinline__ float to_tf32(float x) {
    uint32_t r; asm("cvt.rna.tf32.f32 %0, %1;" : "=r"(r) : "f"(x));
    return __uint_as_float(r);
}

// ---------------------------------------------------------------------------
// Round x to tf32 (rna) once.
// ---------------------------------------------------------------------------
__global__ __launch_bounds__(256) void round_x(const float* __restrict__ x,
                                               float* __restrict__ xr) {
    int i = (blockIdx.x * 256 + threadIdx.x) * 4;
    float4 v = *(const float4*)&x[i];
    *(float4*)&xr[i] = make_float4(to_tf32(v.x), to_tf32(v.y), to_tf32(v.z), to_tf32(v.w));
}

// ---------------------------------------------------------------------------
// Weight transpose + tf32 rounding: W[K][N] -> Wt[N][K]
// ---------------------------------------------------------------------------
__global__ __launch_bounds__(256) void transpose_w(const float* __restrict__ w0,
                                                   const float* __restrict__ w1,
                                                   const float* __restrict__ w2,
                                                   const float* __restrict__ w3,
                                                   float* __restrict__ dst) {
    __shared__ float tile[32][33];
    const int z = blockIdx.z;
    const float* src = (z == 0) ? w0 : (z == 1) ? w1 : (z == 2) ? w2 : w3;
    float* d = dst + (size_t)z * DMODEL * DMODEL;
    const int tx = threadIdx.x, ty = threadIdx.y;
    const int x = blockIdx.x * 32 + tx;
    const int y0 = blockIdx.y * 32;
#pragma unroll
    for (int j = ty; j < 32; j += 8)
        tile[j][tx] = to_tf32(src[(size_t)(y0 + j) * DMODEL + x]);
    __syncthreads();
    const int xo = blockIdx.y * 32 + tx;
    const int yo0 = blockIdx.x * 32;
#pragma unroll
    for (int j = ty; j < 32; j += 8)
        d[(size_t)(yo0 + j) * DMODEL + xo] = tile[tx][j];
}

// ---------------------------------------------------------------------------
// tf32 mma.sync GEMM: C(MxN) = A(MxK, row-major, tf32-rounded) * Wt(NxK)^T
// CTA 128x128x32, 256 threads, 8 warps (2M x 4N), warp tile 64x32.
// cp.async double-buffered. Smem stride 36 floats (conflict-free frags).
// MODE 0: C[row*N + col]; MODE 1: head-major C[((col>>6)*M + row)*64 + (col&63)]
// ---------------------------------------------------------------------------
#define GBK 32
#define STG_FLOATS (128 * 36)

template <int MODE>
__global__ __launch_bounds__(256, 2)
void gemm_mma(const float* __restrict__ A, const float* __restrict__ Bt,
              float* __restrict__ C, int M, int N, int K) {
    extern __shared__ float smf[];
    const uint32_t sbase = smem_u32(smf);
    const int tid = threadIdx.x;
    const int wid = tid >> 5;
    const int lane = tid & 31;
    const int row0 = blockIdx.y * 128;
    const int col0 = blockIdx.x * 128;
    const int wm = (wid & 1) * 64;
    const int wn = (wid >> 1) * 32;
    const int g = lane >> 2;   // 0..7
    const int q = lane & 3;    // 0..3

    const int l_row = tid >> 3;  // + 32*i
    const int l_c   = tid & 7;

    float c[4][4][4];
#pragma unroll
    for (int mt = 0; mt < 4; mt++)
#pragma unroll
        for (int nt = 0; nt < 4; nt++)
#pragma unroll
            for (int r = 0; r < 4; r++) c[mt][nt][r] = 0.f;

    auto stage_load = [&](int kb, int s) {
        const int k0 = kb * GBK;
#pragma unroll
        for (int i = 0; i < 4; i++) {
            int r = l_row + i * 32;
            uint32_t da = sbase + (uint32_t)(s * 2 * STG_FLOATS + r * 36 + l_c * 4) * 4u;
            const float* ga = &A[(size_t)(row0 + r) * K + k0 + l_c * 4];
            asm volatile("cp.async.cg.shared.global [%0], [%1], 16;" :: "r"(da), "l"(ga));
            uint32_t db = da + (uint32_t)STG_FLOATS * 4u;
            const float* gb = &Bt[(size_t)(col0 + r) * K + k0 + l_c * 4];
            asm volatile("cp.async.cg.shared.global [%0], [%1], 16;" :: "r"(db), "l"(gb));
        }
        asm volatile("cp.async.commit_group;");
    };

    const int NK = K / GBK;
    stage_load(0, 0);

    for (int kb = 0; kb < NK; kb++) {
        const int s = kb & 1;
        if (kb + 1 < NK) {
            stage_load(kb + 1, s ^ 1);
            asm volatile("cp.async.wait_group 1;");
        } else {
            asm volatile("cp.async.wait_group 0;");
        }
        __syncthreads();

        const float* As = smf + s * 2 * STG_FLOATS;
        const float* Bs = As + STG_FLOATS;
        const float* pa = &As[(wm + g) * 36 + q];
        const float* pb = &Bs[(wn + g) * 36 + q];

#pragma unroll
        for (int ks = 0; ks < 4; ks++) {
            uint32_t af[4][4], bf[4][2];
#pragma unroll
            for (int mt = 0; mt < 4; mt++) {
                af[mt][0] = __float_as_uint(pa[(mt * 16 + 0) * 36 + ks * 8 + 0]);
                af[mt][1] = __float_as_uint(pa[(mt * 16 + 8) * 36 + ks * 8 + 0]);
                af[mt][2] = __float_as_uint(pa[(mt * 16 + 0) * 36 + ks * 8 + 4]);
                af[mt][3] = __float_as_uint(pa[(mt * 16 + 8) * 36 + ks * 8 + 4]);
            }
#pragma unroll
            for (int nt = 0; nt < 4; nt++) {
                bf[nt][0] = __float_as_uint(pb[(nt * 8) * 36 + ks * 8 + 0]);
                bf[nt][1] = __float_as_uint(pb[(nt * 8) * 36 + ks * 8 + 4]);
            }
#pragma unroll
            for (int mt = 0; mt < 4; mt++)
#pragma unroll
                for (int nt = 0; nt < 4; nt++)
                    asm volatile(
                        "mma.sync.aligned.m16n8k8.row.col.f32.tf32.tf32.f32 "
                        "{%0,%1,%2,%3}, {%4,%5,%6,%7}, {%8,%9}, {%0,%1,%2,%3};"
                        : "+f"(c[mt][nt][0]), "+f"(c[mt][nt][1]),
                          "+f"(c[mt][nt][2]), "+f"(c[mt][nt][3])
                        : "r"(af[mt][0]), "r"(af[mt][1]), "r"(af[mt][2]), "r"(af[mt][3]),
                          "r"(bf[nt][0]), "r"(bf[nt][1]));
        }
        __syncthreads();
    }

    // Epilogue: c0,c1 -> (row, col..col+1); c2,c3 -> (row+8, ...)
#pragma unroll
    for (int mt = 0; mt < 4; mt++) {
#pragma unroll
        for (int hr = 0; hr < 2; hr++) {
            int row = row0 + wm + mt * 16 + g + hr * 8;
#pragma unroll
            for (int nt = 0; nt < 4; nt++) {
                int col = col0 + wn + nt * 8 + q * 2;
                float2 v = make_float2(c[mt][nt][hr * 2], c[mt][nt][hr * 2 + 1]);
                if (MODE == 0) {
                    *(float2*)&C[(size_t)row * N + col] = v;
                } else {
                    int head = col >> 6;
                    *(float2*)&C[((size_t)head * M + row) * 64 + (col & 63)] = v;
                }
            }
        }
    }
}

// ---------------------------------------------------------------------------
// Flash attention, register-tiled + FFMA2 (unchanged except tf32-rounded store).
// ---------------------------------------------------------------------------
__global__ __launch_bounds__(128, 3) void attn_kernel() {
    __shared__ float Qt[64 * 64];
    __shared__ float KtPt[64 * 64];
    __shared__ float Vs[64 * 64];

    const int h  = blockIdx.y;
    const int bx = (int)gridDim.x - 1 - (int)blockIdx.x;
    const int i0 = bx * 64;
    const int t  = threadIdx.x;
    const int tx = t & 7;
    const int ty = t >> 3;
    const int r0 = ty * 4;
    const float slope = exp2f(-0.5f * (float)(h + 1));

    {
        const float* qp = g_q + ((size_t)h * L_SEQ + i0) * HDIM;
#pragma unroll
        for (int idx = t; idx < 1024; idx += 128) {
            int row = idx & 63, dg = idx >> 6;
            float4 v = *(const float4*)&qp[row * 64 + dg * 4];
            Qt[(dg * 4 + 0) * 64 + row] = v.x * 0.125f;
            Qt[(dg * 4 + 1) * 64 + row] = v.y * 0.125f;
            Qt[(dg * 4 + 2) * 64 + row] = v.z * 0.125f;
            Qt[(dg * 4 + 3) * 64 + row] = v.w * 0.125f;
        }
    }

    float m[4], l[4];
    ull o2[4][4];
#pragma unroll
    for (int r = 0; r < 4; r++) {
        m[r] = -INFINITY; l[r] = 0.f;
#pragma unroll
        for (int c = 0; c < 4; c++) o2[r][c] = 0ull;
    }

    for (int kb = 0; kb <= bx; kb++) {
        const int j0 = kb * 64;
        const float* kp = g_k + ((size_t)h * L_SEQ + j0) * HDIM;
        const float* vp = g_v + ((size_t)h * L_SEQ + j0) * HDIM;
        __syncthreads();
#pragma unroll
        for (int idx = t; idx < 1024; idx += 128) {
            int key = idx & 63, dg = idx >> 6;
            float4 v = *(const float4*)&kp[key * 64 + dg * 4];
            KtPt[(dg * 4 + 0) * 64 + key] = v.x;
            KtPt[(dg * 4 + 1) * 64 + key] = v.y;
            KtPt[(dg * 4 + 2) * 64 + key] = v.z;
            KtPt[(dg * 4 + 3) * 64 + key] = v.w;
        }
#pragma unroll
        for (int idx = t; idx < 1024; idx += 128)
            *(float4*)&Vs[idx * 4] = *(const float4*)&vp[idx * 4];
        __syncthreads();

        ull s2[4][4];
#pragma unroll
        for (int r = 0; r < 4; r++)
#pragma unroll
            for (int c = 0; c < 4; c++) s2[r][c] = 0ull;

#pragma unroll 8
        for (int d = 0; d < 64; d++) {
            float4 a = *(const float4*)&Qt[d * 64 + r0];
            F4U2 bb0, bb1;
            bb0.f = *(const float4*)&KtPt[d * 64 + tx * 8];
            bb1.f = *(const float4*)&KtPt[d * 64 + tx * 8 + 4];
            ull b2[4] = {bb0.u[0], bb0.u[1], bb1.u[0], bb1.u[1]};
            float avv[4] = {a.x, a.y, a.z, a.w};
#pragma unroll
            for (int r = 0; r < 4; r++) {
                ull A2 = pk2(avv[r], avv[r]);
#pragma unroll
                for (int c = 0; c < 4; c++)
                    s2[r][c] = ffma2(A2, b2[c], s2[r][c]);
            }
        }

        float s[4][8];
        const bool diag = (kb == bx);
#pragma unroll
        for (int r = 0; r < 4; r++) {
            int ig = i0 + r0 + r;
#pragma unroll
            for (int c = 0; c < 4; c++) {
                float2 f = upk2(s2[r][c]);
                int jg = j0 + tx * 8 + 2 * c;
                s[r][2 * c + 0] = f.x - slope * (float)(ig - jg);
                s[r][2 * c + 1] = f.y - slope * (float)(ig - jg - 1);
                if (diag) {
                    if (jg > ig)     s[r][2 * c + 0] = -INFINITY;
                    if (jg + 1 > ig) s[r][2 * c + 1] = -INFINITY;
                }
            }
        }

        float mt[4];
#pragma unroll
        for (int r = 0; r < 4; r++) {
            float v = s[r][0];
#pragma unroll
            for (int k = 1; k < 8; k++) v = fmaxf(v, s[r][k]);
            v = fmaxf(v, __shfl_xor_sync(0xffffffffu, v, 1));
            v = fmaxf(v, __shfl_xor_sync(0xffffffffu, v, 2));
            v = fmaxf(v, __shfl_xor_sync(0xffffffffu, v, 4));
            mt[r] = fmaxf(m[r], v);
        }
#pragma unroll
        for (int r = 0; r < 4; r++) {
            float corr = __expf(m[r] - mt[r]);
            m[r] = mt[r];
            l[r] *= corr;
            ull c2 = pk2(corr, corr);
#pragma unroll
            for (int c = 0; c < 4; c++) o2[r][c] = fmul2(o2[r][c], c2);
#pragma unroll
            for (int k = 0; k < 8; k++) {
                float p = __expf(s[r][k] - m[r]);
                s[r][k] = p;
                l[r] += p;
            }
        }

        __syncthreads();
#pragma unroll
        for (int kk = 0; kk < 8; kk++) {
            int key = tx * 8 + kk;
            *(float4*)&KtPt[key * 64 + r0] =
                make_float4(s[0][kk], s[1][kk], s[2][kk], s[3][kk]);
        }
        __syncthreads();

#pragma unroll 8
        for (int key = 0; key < 64; key++) {
            float4 a = *(const float4*)&KtPt[key * 64 + r0];
            F4U2 vv0, vv1;
            vv0.f = *(const float4*)&Vs[key * 64 + tx * 8];
            vv1.f = *(const float4*)&Vs[key * 64 + tx * 8 + 4];
            ull v2[4] = {vv0.u[0], vv0.u[1], vv1.u[0], vv1.u[1]};
            float avv[4] = {a.x, a.y, a.z, a.w};
#pragma unroll
            for (int r = 0; r < 4; r++) {
                ull A2 = pk2(avv[r], avv[r]);
#pragma unroll
                for (int c = 0; c < 4; c++)
                    o2[r][c] = ffma2(A2, v2[c], o2[r][c]);
            }
        }
    }

#pragma unroll
    for (int r = 0; r < 4; r++) {
        float lv = l[r];
        lv += __shfl_xor_sync(0xffffffffu, lv, 1);
        lv += __shfl_xor_sync(0xffffffffu, lv, 2);
        lv += __shfl_xor_sync(0xffffffffu, lv, 4);
        float inv = 1.0f / lv;
        float* op = g_attn + (size_t)(i0 + r0 + r) * DMODEL + h * HDIM + tx * 8;
        float2 p0 = upk2(o2[r][0]), p1 = upk2(o2[r][1]);
        float2 p2 = upk2(o2[r][2]), p3 = upk2(o2[r][3]);
        // tf32-round so the output GEMM's HMMA truncation is exact rna rounding
        *(float4*)&op[0] = make_float4(to_tf32(p0.x * inv), to_tf32(p0.y * inv),
                                       to_tf32(p1.x * inv), to_tf32(p1.y * inv));
        *(float4*)&op[4] = make_float4(to_tf32(p2.x * inv), to_tf32(p2.y * inv),
                                       to_tf32(p3.x * inv), to_tf32(p3.y * inv));
    }
}

// ---------------------------------------------------------------------------
extern "C" void kernel_launch(void* const* d_in, const int* in_sizes, int n_in,
                              void* d_out, int out_size) {
    const float* x  = (const float*)d_in[0];
    const float* qw = (const float*)d_in[1];
    const float* kw = (const float*)d_in[2];
    const float* vw = (const float*)d_in[3];
    const float* ow = (const float*)d_in[4];
    float* out = (float*)d_out;

    float *pq, *pk, *pv, *pa, *pwt, *pxr;
    cudaGetSymbolAddress((void**)&pq, g_q);
    cudaGetSymbolAddress((void**)&pk, g_k);
    cudaGetSymbolAddress((void**)&pv, g_v);
    cudaGetSymbolAddress((void**)&pa, g_attn);
    cudaGetSymbolAddress((void**)&pwt, g_wt);
    cudaGetSymbolAddress((void**)&pxr, g_xr);

    const int SMEM_GEMM = 2 * 2 * STG_FLOATS * 4;  // 73728 B
    cudaFuncSetAttribute(gemm_mma<0>, cudaFuncAttributeMaxDynamicSharedMemorySize, SMEM_GEMM);
    cudaFuncSetAttribute(gemm_mma<1>, cudaFuncAttributeMaxDynamicSharedMemorySize, SMEM_GEMM);

    // Pre-round x; transpose + round weights
    round_x<<<(L_SEQ * DMODEL) / (256 * 4), 256>>>(x, pxr);
    dim3 tb(32, 8);
    dim3 tg(DMODEL / 32, DMODEL / 32, 4);
    transpose_w<<<tg, tb>>>(qw, kw, vw, ow, pwt);

    dim3 gp(DMODEL / 128, L_SEQ / 128);
    const size_t WSZ = (size_t)DMODEL * DMODEL;
    gemm_mma<1><<<gp, 256, SMEM_GEMM>>>(pxr, pwt + 0 * WSZ, pq, L_SEQ, DMODEL, DMODEL);
    gemm_mma<1><<<gp, 256, SMEM_GEMM>>>(pxr, pwt + 1 * WSZ, pk, L_SEQ, DMODEL, DMODEL);
    gemm_mma<1><<<gp, 256, SMEM_GEMM>>>(pxr, pwt + 2 * WSZ, pv, L_SEQ, DMODEL, DMODEL);

    dim3 ga(L_SEQ / 64, NHEADS);
    attn_kernel<<<ga, 128>>>();

    gemm_mma<0><<<gp, 256, SMEM_GEMM>>>(pa, pwt + 3 * WSZ, out, L_SEQ, DMODEL, DMODEL);
}

// round 6
// speedup vs baseline: 5.0207x; 5.0207x over previous
#include <cuda_runtime.h>
#include <math.h>
#include <stdint.h>

#define L_SEQ  4096
#define DMODEL 1024
#define NHEADS 16
#define HDIM   64
#define LOG2E  1.4426950408889634f

// Scratch (allocation-free rule: __device__ globals)
__device__ float g_q[NHEADS * L_SEQ * HDIM];   // [h][seq][d], scaled*0.125*log2e, tf32-rounded
__device__ float g_k[NHEADS * L_SEQ * HDIM];   // [h][seq][d], tf32-rounded
__device__ float g_v[NHEADS * HDIM * L_SEQ];   // [h][d][seq]  (TRANSPOSED), tf32-rounded
__device__ float g_attn[L_SEQ * DMODEL];       // [seq][dmodel], tf32-rounded
__device__ float g_wt[4 * DMODEL * DMODEL];    // transposed tf32-rounded weights [N][K]
__device__ float g_xr[L_SEQ * DMODEL];         // tf32-rounded x

__device__ __forceinline__ uint32_t smem_u32(const void* p) {
    uint32_t a;
    asm("{ .reg .u64 t; cvta.to.shared.u64 t, %1; cvt.u32.u64 %0, t; }" : "=r"(a) : "l"(p));
    return a;
}
__device__ __forceinline__ float to_tf32(float x) {
    uint32_t r; asm("cvt.rna.tf32.f32 %0, %1;" : "=r"(r) : "f"(x));
    return __uint_as_float(r);
}
__device__ __forceinline__ float ex2(float x) {
    float y; asm("ex2.approx.f32 %0, %1;" : "=f"(y) : "f"(x)); return y;
}
__device__ __forceinline__ void mma8(float* c, uint32_t a0, uint32_t a1, uint32_t a2,
                                     uint32_t a3, uint32_t b0, uint32_t b1) {
    asm volatile(
        "mma.sync.aligned.m16n8k8.row.col.f32.tf32.tf32.f32 "
        "{%0,%1,%2,%3}, {%4,%5,%6,%7}, {%8,%9}, {%0,%1,%2,%3};"
        : "+f"(c[0]), "+f"(c[1]), "+f"(c[2]), "+f"(c[3])
        : "r"(a0), "r"(a1), "r"(a2), "r"(a3), "r"(b0), "r"(b1));
}

// ---------------------------------------------------------------------------
// Round x to tf32 (rna) once.
// ---------------------------------------------------------------------------
__global__ __launch_bounds__(256) void round_x(const float* __restrict__ x,
                                               float* __restrict__ xr) {
    int i = (blockIdx.x * 256 + threadIdx.x) * 4;
    float4 v = *(const float4*)&x[i];
    *(float4*)&xr[i] = make_float4(to_tf32(v.x), to_tf32(v.y), to_tf32(v.z), to_tf32(v.w));
}

// ---------------------------------------------------------------------------
// Weight transpose + tf32 rounding: W[K][N] -> Wt[N][K]
// ---------------------------------------------------------------------------
__global__ __launch_bounds__(256) void transpose_w(const float* __restrict__ w0,
                                                   const float* __restrict__ w1,
                                                   const float* __restrict__ w2,
                                                   const float* __restrict__ w3,
                                                   float* __restrict__ dst) {
    __shared__ float tile[32][33];
    const int z = blockIdx.z;
    const float* src = (z == 0) ? w0 : (z == 1) ? w1 : (z == 2) ? w2 : w3;
    float* d = dst + (size_t)z * DMODEL * DMODEL;
    const int tx = threadIdx.x, ty = threadIdx.y;
    const int x = blockIdx.x * 32 + tx;
    const int y0 = blockIdx.y * 32;
#pragma unroll
    for (int j = ty; j < 32; j += 8)
        tile[j][tx] = to_tf32(src[(size_t)(y0 + j) * DMODEL + x]);
    __syncthreads();
    const int xo = blockIdx.y * 32 + tx;
    const int yo0 = blockIdx.x * 32;
#pragma unroll
    for (int j = ty; j < 32; j += 8)
        d[(size_t)(yo0 + j) * DMODEL + xo] = tile[tx][j];
}

// ---------------------------------------------------------------------------
// tf32 mma.sync GEMM: C(MxN) = A(MxK) * Wt(NxK)^T. CTA 128x128x32, 8 warps.
// MODE 0: C[row*N+col] (no round)
// MODE 1: head-major C[((col>>6)*M+row)*64+(col&63)], scaled+rounded
// MODE 2: head-transposed C[((col>>6)*64+(col&63))*M+row], rounded (for V)
// ---------------------------------------------------------------------------
#define GBK 32
#define STG_FLOATS (128 * 36)

template <int MODE, bool RND>
__global__ __launch_bounds__(256, 2)
void gemm_mma(const float* __restrict__ A, const float* __restrict__ Bt,
              float* __restrict__ C, int M, int N, int K, float scale) {
    extern __shared__ float smf[];
    const uint32_t sbase = smem_u32(smf);
    const int tid = threadIdx.x;
    const int wid = tid >> 5;
    const int lane = tid & 31;
    const int row0 = blockIdx.y * 128;
    const int col0 = blockIdx.x * 128;
    const int wm = (wid & 1) * 64;
    const int wn = (wid >> 1) * 32;
    const int g = lane >> 2;
    const int q = lane & 3;

    const int l_row = tid >> 3;
    const int l_c   = tid & 7;

    float c[4][4][4];
#pragma unroll
    for (int mt = 0; mt < 4; mt++)
#pragma unroll
        for (int nt = 0; nt < 4; nt++)
#pragma unroll
            for (int r = 0; r < 4; r++) c[mt][nt][r] = 0.f;

    auto stage_load = [&](int kb, int s) {
        const int k0 = kb * GBK;
#pragma unroll
        for (int i = 0; i < 4; i++) {
            int r = l_row + i * 32;
            uint32_t da = sbase + (uint32_t)(s * 2 * STG_FLOATS + r * 36 + l_c * 4) * 4u;
            const float* ga = &A[(size_t)(row0 + r) * K + k0 + l_c * 4];
            asm volatile("cp.async.cg.shared.global [%0], [%1], 16;" :: "r"(da), "l"(ga));
            uint32_t db = da + (uint32_t)STG_FLOATS * 4u;
            const float* gb = &Bt[(size_t)(col0 + r) * K + k0 + l_c * 4];
            asm volatile("cp.async.cg.shared.global [%0], [%1], 16;" :: "r"(db), "l"(gb));
        }
        asm volatile("cp.async.commit_group;");
    };

    const int NK = K / GBK;
    stage_load(0, 0);

    for (int kb = 0; kb < NK; kb++) {
        const int s = kb & 1;
        if (kb + 1 < NK) {
            stage_load(kb + 1, s ^ 1);
            asm volatile("cp.async.wait_group 1;");
        } else {
            asm volatile("cp.async.wait_group 0;");
        }
        __syncthreads();

        const float* As = smf + s * 2 * STG_FLOATS;
        const float* Bs = As + STG_FLOATS;
        const float* pa = &As[(wm + g) * 36 + q];
        const float* pb = &Bs[(wn + g) * 36 + q];

#pragma unroll
        for (int ks = 0; ks < 4; ks++) {
            uint32_t af[4][4], bf[4][2];
#pragma unroll
            for (int mt = 0; mt < 4; mt++) {
                af[mt][0] = __float_as_uint(pa[(mt * 16 + 0) * 36 + ks * 8 + 0]);
                af[mt][1] = __float_as_uint(pa[(mt * 16 + 8) * 36 + ks * 8 + 0]);
                af[mt][2] = __float_as_uint(pa[(mt * 16 + 0) * 36 + ks * 8 + 4]);
                af[mt][3] = __float_as_uint(pa[(mt * 16 + 8) * 36 + ks * 8 + 4]);
            }
#pragma unroll
            for (int nt = 0; nt < 4; nt++) {
                bf[nt][0] = __float_as_uint(pb[(nt * 8) * 36 + ks * 8 + 0]);
                bf[nt][1] = __float_as_uint(pb[(nt * 8) * 36 + ks * 8 + 4]);
            }
#pragma unroll
            for (int mt = 0; mt < 4; mt++)
#pragma unroll
                for (int nt = 0; nt < 4; nt++)
                    mma8(c[mt][nt], af[mt][0], af[mt][1], af[mt][2], af[mt][3],
                         bf[nt][0], bf[nt][1]);
        }
        __syncthreads();
    }

#pragma unroll
    for (int mt = 0; mt < 4; mt++) {
#pragma unroll
        for (int hr = 0; hr < 2; hr++) {
            int row = row0 + wm + mt * 16 + g + hr * 8;
#pragma unroll
            for (int nt = 0; nt < 4; nt++) {
                int col = col0 + wn + nt * 8 + q * 2;
                float vx = c[mt][nt][hr * 2] * scale;
                float vy = c[mt][nt][hr * 2 + 1] * scale;
                if (RND) { vx = to_tf32(vx); vy = to_tf32(vy); }
                if (MODE == 0) {
                    *(float2*)&C[(size_t)row * N + col] = make_float2(vx, vy);
                } else if (MODE == 1) {
                    int head = col >> 6;
                    *(float2*)&C[((size_t)head * M + row) * 64 + (col & 63)] =
                        make_float2(vx, vy);
                } else {
                    int head = col >> 6, d0 = col & 63;
                    C[((size_t)(head * 64 + d0)) * M + row] = vx;
                    C[((size_t)(head * 64 + d0 + 1)) * M + row] = vy;
                }
            }
        }
    }
}

// ---------------------------------------------------------------------------
// Tensor-core flash attention (m16n8k8 tf32) + ALiBi + causal, exp2 domain.
// Block = (head, 128 q-rows), 8 warps x 16 rows. 64-key tiles, double-buffered
// cp.async K/V staging. P: C-frag -> A-frag via shfl (no smem round-trip).
// ---------------------------------------------------------------------------
#define PADK 68
#define AT_QOFF   0
#define AT_KOFF   (128 * PADK)
#define AT_VOFF   (AT_KOFF + 2 * 64 * PADK)
#define AT_FLOATS (AT_VOFF + 2 * 64 * PADK)   // 26112 floats = 104448 B

__global__ __launch_bounds__(256, 2) void attn_mma() {
    extern __shared__ float sm[];
    const uint32_t sb = smem_u32(sm);
    const int h  = blockIdx.y;
    const int bx = (int)gridDim.x - 1 - (int)blockIdx.x;  // big tiles first
    const int i0 = bx * 128;
    const int tid = threadIdx.x;
    const int w = tid >> 5;
    const int lane = tid & 31;
    const int g = lane >> 2, q = lane & 3;
    const int qr = w * 16;
    const float slope2 = ex2(-0.5f * (float)(h + 1)) * LOG2E;

    const float* Qs = sm + AT_QOFF;

    auto load_tile = [&](int t, int s) {
        const int j0 = t * 64;
        const float* kp = g_k + ((size_t)h * L_SEQ + j0) * HDIM;
        const float* vp = g_v + (size_t)h * HDIM * L_SEQ + j0;
        const uint32_t kd = sb + (AT_KOFF + s * 64 * PADK) * 4u;
        const uint32_t vd = sb + (AT_VOFF + s * 64 * PADK) * 4u;
#pragma unroll
        for (int i = 0; i < 4; i++) {
            int cc = tid + i * 256;
            int row = cc >> 4, c16 = cc & 15;
            asm volatile("cp.async.cg.shared.global [%0], [%1], 16;"
                         :: "r"(kd + (uint32_t)(row * PADK + c16 * 4) * 4u),
                            "l"(kp + (size_t)row * HDIM + c16 * 4));
            asm volatile("cp.async.cg.shared.global [%0], [%1], 16;"
                         :: "r"(vd + (uint32_t)(row * PADK + c16 * 4) * 4u),
                            "l"(vp + (size_t)row * L_SEQ + c16 * 4));
        }
        asm volatile("cp.async.commit_group;");
    };

    // Prologue: Q (2048 chunks) + tile 0, one group
    {
        const float* qp = g_q + ((size_t)h * L_SEQ + i0) * HDIM;
        const uint32_t qd = sb + AT_QOFF * 4u;
#pragma unroll
        for (int i = 0; i < 8; i++) {
            int cc = tid + i * 256;
            int row = cc >> 4, c16 = cc & 15;
            asm volatile("cp.async.cg.shared.global [%0], [%1], 16;"
                         :: "r"(qd + (uint32_t)(row * PADK + c16 * 4) * 4u),
                            "l"(qp + (size_t)row * HDIM + c16 * 4));
        }
        load_tile(0, 0);
    }

    float mA = -INFINITY, mB = -INFINITY, lA = 0.f, lB = 0.f;
    float O[8][4];
#pragma unroll
    for (int nt = 0; nt < 8; nt++)
#pragma unroll
        for (int r = 0; r < 4; r++) O[nt][r] = 0.f;

    const int ntiles = 2 * bx + 2;
    const int iA = i0 + qr + g;
    const int iB = iA + 8;

    for (int t = 0; t < ntiles; t++) {
        if (t + 1 < ntiles) {
            load_tile(t + 1, (t + 1) & 1);
            asm volatile("cp.async.wait_group 1;");
        } else {
            asm volatile("cp.async.wait_group 0;");
        }
        __syncthreads();

        const int j0 = t * 64;
        if (j0 <= i0 + qr + 15) {  // warp has >=1 unmasked row this tile
            const float* Ks = sm + AT_KOFF + (t & 1) * 64 * PADK;
            const float* Vs = sm + AT_VOFF + (t & 1) * 64 * PADK;

            // ---- S = Q K^T ----
            float s[8][4];
#pragma unroll
            for (int nt = 0; nt < 8; nt++)
#pragma unroll
                for (int r = 0; r < 4; r++) s[nt][r] = 0.f;

#pragma unroll
            for (int ks = 0; ks < 8; ks++) {
                uint32_t a0 = __float_as_uint(Qs[(qr + g) * PADK + ks * 8 + q]);
                uint32_t a1 = __float_as_uint(Qs[(qr + g + 8) * PADK + ks * 8 + q]);
                uint32_t a2 = __float_as_uint(Qs[(qr + g) * PADK + ks * 8 + q + 4]);
                uint32_t a3 = __float_as_uint(Qs[(qr + g + 8) * PADK + ks * 8 + q + 4]);
#pragma unroll
                for (int nt = 0; nt < 8; nt++) {
                    uint32_t b0 = __float_as_uint(Ks[(nt * 8 + g) * PADK + ks * 8 + q]);
                    uint32_t b1 = __float_as_uint(Ks[(nt * 8 + g) * PADK + ks * 8 + q + 4]);
                    mma8(s[nt], a0, a1, a2, a3, b0, b1);
                }
            }

            // ---- ALiBi + causal mask (log2 domain) ----
            const bool needmask = (j0 + 63 > i0 + qr);
#pragma unroll
            for (int nt = 0; nt < 8; nt++) {
                int j = j0 + nt * 8 + 2 * q;
                s[nt][0] -= slope2 * (float)(iA - j);
                s[nt][1] -= slope2 * (float)(iA - j - 1);
                s[nt][2] -= slope2 * (float)(iB - j);
                s[nt][3] -= slope2 * (float)(iB - j - 1);
                if (needmask) {
                    if (j > iA)     s[nt][0] = -INFINITY;
                    if (j + 1 > iA) s[nt][1] = -INFINITY;
                    if (j > iB)     s[nt][2] = -INFINITY;
                    if (j + 1 > iB) s[nt][3] = -INFINITY;
                }
            }

            // ---- online softmax ----
            float mxA = -INFINITY, mxB = -INFINITY;
#pragma unroll
            for (int nt = 0; nt < 8; nt++) {
                mxA = fmaxf(mxA, fmaxf(s[nt][0], s[nt][1]));
                mxB = fmaxf(mxB, fmaxf(s[nt][2], s[nt][3]));
            }
            mxA = fmaxf(mxA, __shfl_xor_sync(0xffffffffu, mxA, 1));
            mxA = fmaxf(mxA, __shfl_xor_sync(0xffffffffu, mxA, 2));
            mxB = fmaxf(mxB, __shfl_xor_sync(0xffffffffu, mxB, 1));
            mxB = fmaxf(mxB, __shfl_xor_sync(0xffffffffu, mxB, 2));
            const float mAn = fmaxf(mA, mxA), mBn = fmaxf(mB, mxB);
            const float cA = ex2(mA - mAn), cB = ex2(mB - mBn);
            mA = mAn; mB = mBn;
            lA *= cA; lB *= cB;
#pragma unroll
            for (int nt = 0; nt < 8; nt++) {
                O[nt][0] *= cA; O[nt][1] *= cA;
                O[nt][2] *= cB; O[nt][3] *= cB;
            }
#pragma unroll
            for (int nt = 0; nt < 8; nt++) {
                float p0 = to_tf32(ex2(s[nt][0] - mA));
                float p1 = to_tf32(ex2(s[nt][1] - mA));
                float p2 = to_tf32(ex2(s[nt][2] - mB));
                float p3 = to_tf32(ex2(s[nt][3] - mB));
                s[nt][0] = p0; s[nt][1] = p1; s[nt][2] = p2; s[nt][3] = p3;
                lA += p0 + p1; lB += p2 + p3;
            }

            // ---- O += P V ---- (P C-frag -> A-frag via shfl)
            const int srcA = (lane & ~3) | (q >> 1);
#pragma unroll
            for (int ks = 0; ks < 8; ks++) {
                float t0 = __shfl_sync(0xffffffffu, s[ks][0], srcA);
                float t1 = __shfl_sync(0xffffffffu, s[ks][1], srcA);
                float t2 = __shfl_sync(0xffffffffu, s[ks][2], srcA);
                float t3 = __shfl_sync(0xffffffffu, s[ks][3], srcA);
                float u0 = __shfl_sync(0xffffffffu, s[ks][0], srcA + 2);
                float u1 = __shfl_sync(0xffffffffu, s[ks][1], srcA + 2);
                float u2 = __shfl_sync(0xffffffffu, s[ks][2], srcA + 2);
                float u3 = __shfl_sync(0xffffffffu, s[ks][3], srcA + 2);
                uint32_t a0 = __float_as_uint((q & 1) ? t1 : t0);
                uint32_t a1 = __float_as_uint((q & 1) ? t3 : t2);
                uint32_t a2 = __float_as_uint((q & 1) ? u1 : u0);
                uint32_t a3 = __float_as_uint((q & 1) ? u3 : u2);
#pragma unroll
                for (int nt = 0; nt < 8; nt++) {
                    uint32_t b0 = __float_as_uint(Vs[(nt * 8 + g) * PADK + ks * 8 + q]);
                    uint32_t b1 = __float_as_uint(Vs[(nt * 8 + g) * PADK + ks * 8 + q + 4]);
                    mma8(O[nt], a0, a1, a2, a3, b0, b1);
                }
            }
        }
        __syncthreads();
    }

    // ---- finalize ----
    lA += __shfl_xor_sync(0xffffffffu, lA, 1);
    lA += __shfl_xor_sync(0xffffffffu, lA, 2);
    lB += __shfl_xor_sync(0xffffffffu, lB, 1);
    lB += __shfl_xor_sync(0xffffffffu, lB, 2);
    const float invA = 1.0f / lA, invB = 1.0f / lB;
#pragma unroll
    for (int nt = 0; nt < 8; nt++) {
        int col = h * HDIM + nt * 8 + 2 * q;
        *(float2*)&g_attn[(size_t)iA * DMODEL + col] =
            make_float2(to_tf32(O[nt][0] * invA), to_tf32(O[nt][1] * invA));
        *(float2*)&g_attn[(size_t)iB * DMODEL + col] =
            make_float2(to_tf32(O[nt][2] * invB), to_tf32(O[nt][3] * invB));
    }
}

// ---------------------------------------------------------------------------
extern "C" void kernel_launch(void* const* d_in, const int* in_sizes, int n_in,
                              void* d_out, int out_size) {
    const float* x  = (const float*)d_in[0];
    const float* qw = (const float*)d_in[1];
    const float* kw = (const float*)d_in[2];
    const float* vw = (const float*)d_in[3];
    const float* ow = (const float*)d_in[4];
    float* out = (float*)d_out;

    float *pq, *pk, *pv, *pa, *pwt, *pxr;
    cudaGetSymbolAddress((void**)&pq, g_q);
    cudaGetSymbolAddress((void**)&pk, g_k);
    cudaGetSymbolAddress((void**)&pv, g_v);
    cudaGetSymbolAddress((void**)&pa, g_attn);
    cudaGetSymbolAddress((void**)&pwt, g_wt);
    cudaGetSymbolAddress((void**)&pxr, g_xr);

    const int SMEM_GEMM = 2 * 2 * STG_FLOATS * 4;   // 73728 B
    const int SMEM_ATTN = AT_FLOATS * 4;            // 104448 B
    cudaFuncSetAttribute(gemm_mma<0, false>, cudaFuncAttributeMaxDynamicSharedMemorySize, SMEM_GEMM);
    cudaFuncSetAttribute(gemm_mma<1, true>,  cudaFuncAttributeMaxDynamicSharedMemorySize, SMEM_GEMM);
    cudaFuncSetAttribute(gemm_mma<2, true>,  cudaFuncAttributeMaxDynamicSharedMemorySize, SMEM_GEMM);
    cudaFuncSetAttribute(attn_mma, cudaFuncAttributeMaxDynamicSharedMemorySize, SMEM_ATTN);

    round_x<<<(L_SEQ * DMODEL) / (256 * 4), 256>>>(x, pxr);
    dim3 tb(32, 8);
    dim3 tg(DMODEL / 32, DMODEL / 32, 4);
    transpose_w<<<tg, tb>>>(qw, kw, vw, ow, pwt);

    dim3 gp(DMODEL / 128, L_SEQ / 128);
    const size_t WSZ = (size_t)DMODEL * DMODEL;
    const float qscale = 0.125f * LOG2E;
    gemm_mma<1, true><<<gp, 256, SMEM_GEMM>>>(pxr, pwt + 0 * WSZ, pq, L_SEQ, DMODEL, DMODEL, qscale);
    gemm_mma<1, true><<<gp, 256, SMEM_GEMM>>>(pxr, pwt + 1 * WSZ, pk, L_SEQ, DMODEL, DMODEL, 1.0f);
    gemm_mma<2, true><<<gp, 256, SMEM_GEMM>>>(pxr, pwt + 2 * WSZ, pv, L_SEQ, DMODEL, DMODEL, 1.0f);

    dim3 ga(L_SEQ / 128, NHEADS);
    attn_mma<<<ga, 256, SMEM_ATTN>>>();

    gemm_mma<0, false><<<gp, 256, SMEM_GEMM>>>(pa, pwt + 3 * WSZ, out, L_SEQ, DMODEL, DMODEL, 1.0f);
}

// round 7
// speedup vs baseline: 5.0478x; 1.0054x over previous
#include <cuda_runtime.h>
#include <math.h>
#include <stdint.h>

#define L_SEQ  4096
#define DMODEL 1024
#define NHEADS 16
#define HDIM   64
#define LOG2E  1.4426950408889634f

// Scratch (allocation-free rule: __device__ globals)
__device__ float g_q[NHEADS * L_SEQ * HDIM];   // [h][seq][d], scaled*0.125*log2e, tf32-rounded
__device__ float g_k[NHEADS * L_SEQ * HDIM];   // [h][seq][d], tf32-rounded
__device__ float g_v[NHEADS * HDIM * L_SEQ];   // [h][d][seq]  (TRANSPOSED), tf32-rounded
__device__ float g_attn[L_SEQ * DMODEL];       // [seq][dmodel], tf32-rounded
__device__ float g_wt[4 * DMODEL * DMODEL];    // transposed tf32-rounded weights [N][K]
__device__ float g_xr[L_SEQ * DMODEL];         // tf32-rounded x

__device__ __forceinline__ uint32_t smem_u32(const void* p) {
    uint32_t a;
    asm("{ .reg .u64 t; cvta.to.shared.u64 t, %1; cvt.u32.u64 %0, t; }" : "=r"(a) : "l"(p));
    return a;
}
__device__ __forceinline__ float to_tf32(float x) {
    uint32_t r; asm("cvt.rna.tf32.f32 %0, %1;" : "=r"(r) : "f"(x));
    return __uint_as_float(r);
}
__device__ __forceinline__ float ex2(float x) {
    float y; asm("ex2.approx.f32 %0, %1;" : "=f"(y) : "f"(x)); return y;
}
__device__ __forceinline__ void mma8(float* c, uint32_t a0, uint32_t a1, uint32_t a2,
                                     uint32_t a3, uint32_t b0, uint32_t b1) {
    asm volatile(
        "mma.sync.aligned.m16n8k8.row.col.f32.tf32.tf32.f32 "
        "{%0,%1,%2,%3}, {%4,%5,%6,%7}, {%8,%9}, {%0,%1,%2,%3};"
        : "+f"(c[0]), "+f"(c[1]), "+f"(c[2]), "+f"(c[3])
        : "r"(a0), "r"(a1), "r"(a2), "r"(a3), "r"(b0), "r"(b1));
}

// ---------------------------------------------------------------------------
// Round x to tf32 (rna) once.
// ---------------------------------------------------------------------------
__global__ __launch_bounds__(256) void round_x(const float* __restrict__ x,
                                               float* __restrict__ xr) {
    int i = (blockIdx.x * 256 + threadIdx.x) * 4;
    float4 v = *(const float4*)&x[i];
    *(float4*)&xr[i] = make_float4(to_tf32(v.x), to_tf32(v.y), to_tf32(v.z), to_tf32(v.w));
}

// ---------------------------------------------------------------------------
// Weight transpose + tf32 rounding: W[K][N] -> Wt[N][K]
// ---------------------------------------------------------------------------
__global__ __launch_bounds__(256) void transpose_w(const float* __restrict__ w0,
                                                   const float* __restrict__ w1,
                                                   const float* __restrict__ w2,
                                                   const float* __restrict__ w3,
                                                   float* __restrict__ dst) {
    __shared__ float tile[32][33];
    const int z = blockIdx.z;
    const float* src = (z == 0) ? w0 : (z == 1) ? w1 : (z == 2) ? w2 : w3;
    float* d = dst + (size_t)z * DMODEL * DMODEL;
    const int tx = threadIdx.x, ty = threadIdx.y;
    const int x = blockIdx.x * 32 + tx;
    const int y0 = blockIdx.y * 32;
#pragma unroll
    for (int j = ty; j < 32; j += 8)
        tile[j][tx] = to_tf32(src[(size_t)(y0 + j) * DMODEL + x]);
    __syncthreads();
    const int xo = blockIdx.y * 32 + tx;
    const int yo0 = blockIdx.x * 32;
#pragma unroll
    for (int j = ty; j < 32; j += 8)
        d[(size_t)(yo0 + j) * DMODEL + xo] = tile[tx][j];
}

// ---------------------------------------------------------------------------
// tf32 mma.sync GEMM core: CTA 128x128x32, 8 warps, 3-stage cp.async pipeline
// with ONE __syncthreads per k-iteration.
// FUSED=true: grid.z selects weight + destination + epilogue mode:
//   z=0 -> g_q head-major, scaled by qscale, tf32-rounded
//   z=1 -> g_k head-major, tf32-rounded
//   z=2 -> g_v head-TRANSPOSED, tf32-rounded
// FUSED=false: C[row*N+col], no rounding.
// ---------------------------------------------------------------------------
#define GBK 32
#define STG_FLOATS (128 * 36)            // one operand (A or B) per stage
#define SMEM_GEMM3 (3 * 2 * STG_FLOATS * 4)

template <bool FUSED>
__global__ __launch_bounds__(256, 2)
void gemm_mma(const float* __restrict__ A, const float* __restrict__ WtBase,
              float* __restrict__ C0, float* __restrict__ C1, float* __restrict__ C2,
              int M, int N, int K, float qscale) {
    extern __shared__ float smf[];
    const uint32_t sbase = smem_u32(smf);
    const int tid = threadIdx.x;
    const int wid = tid >> 5;
    const int lane = tid & 31;
    const int row0 = blockIdx.y * 128;
    const int col0 = blockIdx.x * 128;
    const int z = FUSED ? (int)blockIdx.z : 0;
    const float* Bt = WtBase + (size_t)z * DMODEL * DMODEL;
    const int wm = (wid & 1) * 64;
    const int wn = (wid >> 1) * 32;
    const int g = lane >> 2;
    const int q = lane & 3;

    const int l_row = tid >> 3;
    const int l_c   = tid & 7;

    float c[4][4][4];
#pragma unroll
    for (int mt = 0; mt < 4; mt++)
#pragma unroll
        for (int nt = 0; nt < 4; nt++)
#pragma unroll
            for (int r = 0; r < 4; r++) c[mt][nt][r] = 0.f;

    auto stage_load = [&](int kb, int s) {
        const int k0 = kb * GBK;
#pragma unroll
        for (int i = 0; i < 4; i++) {
            int r = l_row + i * 32;
            uint32_t da = sbase + (uint32_t)(s * 2 * STG_FLOATS + r * 36 + l_c * 4) * 4u;
            const float* ga = &A[(size_t)(row0 + r) * K + k0 + l_c * 4];
            asm volatile("cp.async.cg.shared.global [%0], [%1], 16;" :: "r"(da), "l"(ga));
            uint32_t db = da + (uint32_t)STG_FLOATS * 4u;
            const float* gb = &Bt[(size_t)(col0 + r) * K + k0 + l_c * 4];
            asm volatile("cp.async.cg.shared.global [%0], [%1], 16;" :: "r"(db), "l"(gb));
        }
        asm volatile("cp.async.commit_group;");
    };

    const int NK = K / GBK;
    stage_load(0, 0);
    stage_load(1, 1);

    int s = 0;
    for (int kb = 0; kb < NK; kb++) {
        if (kb + 1 < NK) {
            asm volatile("cp.async.wait_group 1;");
        } else {
            asm volatile("cp.async.wait_group 0;");
        }
        __syncthreads();
        // Issue next-next stage: overwrites stage consumed at kb-1; safe after sync.
        if (kb + 2 < NK) stage_load(kb + 2, (kb + 2) % 3);

        const float* As = smf + s * 2 * STG_FLOATS;
        const float* Bs = As + STG_FLOATS;
        const float* pa = &As[(wm + g) * 36 + q];
        const float* pb = &Bs[(wn + g) * 36 + q];

#pragma unroll
        for (int ks = 0; ks < 4; ks++) {
            uint32_t af[4][4], bf[4][2];
#pragma unroll
            for (int mt = 0; mt < 4; mt++) {
                af[mt][0] = __float_as_uint(pa[(mt * 16 + 0) * 36 + ks * 8 + 0]);
                af[mt][1] = __float_as_uint(pa[(mt * 16 + 8) * 36 + ks * 8 + 0]);
                af[mt][2] = __float_as_uint(pa[(mt * 16 + 0) * 36 + ks * 8 + 4]);
                af[mt][3] = __float_as_uint(pa[(mt * 16 + 8) * 36 + ks * 8 + 4]);
            }
#pragma unroll
            for (int nt = 0; nt < 4; nt++) {
                bf[nt][0] = __float_as_uint(pb[(nt * 8) * 36 + ks * 8 + 0]);
                bf[nt][1] = __float_as_uint(pb[(nt * 8) * 36 + ks * 8 + 4]);
            }
#pragma unroll
            for (int mt = 0; mt < 4; mt++)
#pragma unroll
                for (int nt = 0; nt < 4; nt++)
                    mma8(c[mt][nt], af[mt][0], af[mt][1], af[mt][2], af[mt][3],
                         bf[nt][0], bf[nt][1]);
        }
        s = (s + 1) % 3;
    }

    const float scale = (FUSED && z == 0) ? qscale : 1.0f;
#pragma unroll
    for (int mt = 0; mt < 4; mt++) {
#pragma unroll
        for (int hr = 0; hr < 2; hr++) {
            int row = row0 + wm + mt * 16 + g + hr * 8;
#pragma unroll
            for (int nt = 0; nt < 4; nt++) {
                int col = col0 + wn + nt * 8 + q * 2;
                float vx = c[mt][nt][hr * 2] * scale;
                float vy = c[mt][nt][hr * 2 + 1] * scale;
                if (!FUSED) {
                    *(float2*)&C0[(size_t)row * N + col] = make_float2(vx, vy);
                } else {
                    vx = to_tf32(vx); vy = to_tf32(vy);
                    int head = col >> 6, d0 = col & 63;
                    if (z == 2) {
                        C2[((size_t)(head * 64 + d0)) * M + row] = vx;
                        C2[((size_t)(head * 64 + d0 + 1)) * M + row] = vy;
                    } else {
                        float* C = (z == 0) ? C0 : C1;
                        *(float2*)&C[((size_t)head * M + row) * 64 + d0] =
                            make_float2(vx, vy);
                    }
                }
            }
        }
    }
}

// ---------------------------------------------------------------------------
// Tensor-core flash attention (m16n8k8 tf32) + ALiBi + causal, exp2 domain.
// Block = (head, 128 q-rows), 8 warps x 16 rows. 64-key tiles, double-buffered
// cp.async K/V staging. P: C-frag -> A-frag via shfl (no smem round-trip).
// ---------------------------------------------------------------------------
#define PADK 68
#define AT_QOFF   0
#define AT_KOFF   (128 * PADK)
#define AT_VOFF   (AT_KOFF + 2 * 64 * PADK)
#define AT_FLOATS (AT_VOFF + 2 * 64 * PADK)   // 26112 floats = 104448 B

__global__ __launch_bounds__(256, 2) void attn_mma() {
    extern __shared__ float sm[];
    const uint32_t sb = smem_u32(sm);
    const int h  = blockIdx.y;
    const int bx = (int)gridDim.x - 1 - (int)blockIdx.x;  // big tiles first
    const int i0 = bx * 128;
    const int tid = threadIdx.x;
    const int w = tid >> 5;
    const int lane = tid & 31;
    const int g = lane >> 2, q = lane & 3;
    const int qr = w * 16;
    const float slope2 = ex2(-0.5f * (float)(h + 1)) * LOG2E;

    const float* Qs = sm + AT_QOFF;

    auto load_tile = [&](int t, int s) {
        const int j0 = t * 64;
        const float* kp = g_k + ((size_t)h * L_SEQ + j0) * HDIM;
        const float* vp = g_v + (size_t)h * HDIM * L_SEQ + j0;
        const uint32_t kd = sb + (AT_KOFF + s * 64 * PADK) * 4u;
        const uint32_t vd = sb + (AT_VOFF + s * 64 * PADK) * 4u;
#pragma unroll
        for (int i = 0; i < 4; i++) {
            int cc = tid + i * 256;
            int row = cc >> 4, c16 = cc & 15;
            asm volatile("cp.async.cg.shared.global [%0], [%1], 16;"
                         :: "r"(kd + (uint32_t)(row * PADK + c16 * 4) * 4u),
                            "l"(kp + (size_t)row * HDIM + c16 * 4));
            asm volatile("cp.async.cg.shared.global [%0], [%1], 16;"
                         :: "r"(vd + (uint32_t)(row * PADK + c16 * 4) * 4u),
                            "l"(vp + (size_t)row * L_SEQ + c16 * 4));
        }
        asm volatile("cp.async.commit_group;");
    };

    {
        const float* qp = g_q + ((size_t)h * L_SEQ + i0) * HDIM;
        const uint32_t qd = sb + AT_QOFF * 4u;
#pragma unroll
        for (int i = 0; i < 8; i++) {
            int cc = tid + i * 256;
            int row = cc >> 4, c16 = cc & 15;
            asm volatile("cp.async.cg.shared.global [%0], [%1], 16;"
                         :: "r"(qd + (uint32_t)(row * PADK + c16 * 4) * 4u),
                            "l"(qp + (size_t)row * HDIM + c16 * 4));
        }
        load_tile(0, 0);
    }

    float mA = -INFINITY, mB = -INFINITY, lA = 0.f, lB = 0.f;
    float O[8][4];
#pragma unroll
    for (int nt = 0; nt < 8; nt++)
#pragma unroll
        for (int r = 0; r < 4; r++) O[nt][r] = 0.f;

    const int ntiles = 2 * bx + 2;
    const int iA = i0 + qr + g;
    const int iB = iA + 8;

    for (int t = 0; t < ntiles; t++) {
        if (t + 1 < ntiles) {
            load_tile(t + 1, (t + 1) & 1);
            asm volatile("cp.async.wait_group 1;");
        } else {
            asm volatile("cp.async.wait_group 0;");
        }
        __syncthreads();

        const int j0 = t * 64;
        if (j0 <= i0 + qr + 15) {
            const float* Ks = sm + AT_KOFF + (t & 1) * 64 * PADK;
            const float* Vs = sm + AT_VOFF + (t & 1) * 64 * PADK;

            float s[8][4];
#pragma unroll
            for (int nt = 0; nt < 8; nt++)
#pragma unroll
                for (int r = 0; r < 4; r++) s[nt][r] = 0.f;

#pragma unroll
            for (int ks = 0; ks < 8; ks++) {
                uint32_t a0 = __float_as_uint(Qs[(qr + g) * PADK + ks * 8 + q]);
                uint32_t a1 = __float_as_uint(Qs[(qr + g + 8) * PADK + ks * 8 + q]);
                uint32_t a2 = __float_as_uint(Qs[(qr + g) * PADK + ks * 8 + q + 4]);
                uint32_t a3 = __float_as_uint(Qs[(qr + g + 8) * PADK + ks * 8 + q + 4]);
#pragma unroll
                for (int nt = 0; nt < 8; nt++) {
                    uint32_t b0 = __float_as_uint(Ks[(nt * 8 + g) * PADK + ks * 8 + q]);
                    uint32_t b1 = __float_as_uint(Ks[(nt * 8 + g) * PADK + ks * 8 + q + 4]);
                    mma8(s[nt], a0, a1, a2, a3, b0, b1);
                }
            }

            const bool needmask = (j0 + 63 > i0 + qr);
#pragma unroll
            for (int nt = 0; nt < 8; nt++) {
                int j = j0 + nt * 8 + 2 * q;
                s[nt][0] -= slope2 * (float)(iA - j);
                s[nt][1] -= slope2 * (float)(iA - j - 1);
                s[nt][2] -= slope2 * (float)(iB - j);
                s[nt][3] -= slope2 * (float)(iB - j - 1);
                if (needmask) {
                    if (j > iA)     s[nt][0] = -INFINITY;
                    if (j + 1 > iA) s[nt][1] = -INFINITY;
                    if (j > iB)     s[nt][2] = -INFINITY;
                    if (j + 1 > iB) s[nt][3] = -INFINITY;
                }
            }

            float mxA = -INFINITY, mxB = -INFINITY;
#pragma unroll
            for (int nt = 0; nt < 8; nt++) {
                mxA = fmaxf(mxA, fmaxf(s[nt][0], s[nt][1]));
                mxB = fmaxf(mxB, fmaxf(s[nt][2], s[nt][3]));
            }
            mxA = fmaxf(mxA, __shfl_xor_sync(0xffffffffu, mxA, 1));
            mxA = fmaxf(mxA, __shfl_xor_sync(0xffffffffu, mxA, 2));
            mxB = fmaxf(mxB, __shfl_xor_sync(0xffffffffu, mxB, 1));
            mxB = fmaxf(mxB, __shfl_xor_sync(0xffffffffu, mxB, 2));
            const float mAn = fmaxf(mA, mxA), mBn = fmaxf(mB, mxB);
            const float cA = ex2(mA - mAn), cB = ex2(mB - mBn);
            mA = mAn; mB = mBn;
            lA *= cA; lB *= cB;
#pragma unroll
            for (int nt = 0; nt < 8; nt++) {
                O[nt][0] *= cA; O[nt][1] *= cA;
                O[nt][2] *= cB; O[nt][3] *= cB;
            }
#pragma unroll
            for (int nt = 0; nt < 8; nt++) {
                float p0 = to_tf32(ex2(s[nt][0] - mA));
                float p1 = to_tf32(ex2(s[nt][1] - mA));
                float p2 = to_tf32(ex2(s[nt][2] - mB));
                float p3 = to_tf32(ex2(s[nt][3] - mB));
                s[nt][0] = p0; s[nt][1] = p1; s[nt][2] = p2; s[nt][3] = p3;
                lA += p0 + p1; lB += p2 + p3;
            }

            const int srcA = (lane & ~3) | (q >> 1);
#pragma unroll
            for (int ks = 0; ks < 8; ks++) {
                float t0 = __shfl_sync(0xffffffffu, s[ks][0], srcA);
                float t1 = __shfl_sync(0xffffffffu, s[ks][1], srcA);
                float t2 = __shfl_sync(0xffffffffu, s[ks][2], srcA);
                float t3 = __shfl_sync(0xffffffffu, s[ks][3], srcA);
                float u0 = __shfl_sync(0xffffffffu, s[ks][0], srcA + 2);
                float u1 = __shfl_sync(0xffffffffu, s[ks][1], srcA + 2);
                float u2 = __shfl_sync(0xffffffffu, s[ks][2], srcA + 2);
                float u3 = __shfl_sync(0xffffffffu, s[ks][3], srcA + 2);
                uint32_t a0 = __float_as_uint((q & 1) ? t1 : t0);
                uint32_t a1 = __float_as_uint((q & 1) ? t3 : t2);
                uint32_t a2 = __float_as_uint((q & 1) ? u1 : u0);
                uint32_t a3 = __float_as_uint((q & 1) ? u3 : u2);
#pragma unroll
                for (int nt = 0; nt < 8; nt++) {
                    uint32_t b0 = __float_as_uint(Vs[(nt * 8 + g) * PADK + ks * 8 + q]);
                    uint32_t b1 = __float_as_uint(Vs[(nt * 8 + g) * PADK + ks * 8 + q + 4]);
                    mma8(O[nt], a0, a1, a2, a3, b0, b1);
                }
            }
        }
        __syncthreads();
    }

    lA += __shfl_xor_sync(0xffffffffu, lA, 1);
    lA += __shfl_xor_sync(0xffffffffu, lA, 2);
    lB += __shfl_xor_sync(0xffffffffu, lB, 1);
    lB += __shfl_xor_sync(0xffffffffu, lB, 2);
    const float invA = 1.0f / lA, invB = 1.0f / lB;
#pragma unroll
    for (int nt = 0; nt < 8; nt++) {
        int col = h * HDIM + nt * 8 + 2 * q;
        *(float2*)&g_attn[(size_t)iA * DMODEL + col] =
            make_float2(to_tf32(O[nt][0] * invA), to_tf32(O[nt][1] * invA));
        *(float2*)&g_attn[(size_t)iB * DMODEL + col] =
            make_float2(to_tf32(O[nt][2] * invB), to_tf32(O[nt][3] * invB));
    }
}

// ---------------------------------------------------------------------------
extern "C" void kernel_launch(void* const* d_in, const int* in_sizes, int n_in,
                              void* d_out, int out_size) {
    const float* x  = (const float*)d_in[0];
    const float* qw = (const float*)d_in[1];
    const float* kw = (const float*)d_in[2];
    const float* vw = (const float*)d_in[3];
    const float* ow = (const float*)d_in[4];
    float* out = (float*)d_out;

    float *pq, *pk, *pv, *pa, *pwt, *pxr;
    cudaGetSymbolAddress((void**)&pq, g_q);
    cudaGetSymbolAddress((void**)&pk, g_k);
    cudaGetSymbolAddress((void**)&pv, g_v);
    cudaGetSymbolAddress((void**)&pa, g_attn);
    cudaGetSymbolAddress((void**)&pwt, g_wt);
    cudaGetSymbolAddress((void**)&pxr, g_xr);

    const int SMEM_ATTN = AT_FLOATS * 4;  // 104448 B
    cudaFuncSetAttribute(gemm_mma<true>,  cudaFuncAttributeMaxDynamicSharedMemorySize, SMEM_GEMM3);
    cudaFuncSetAttribute(gemm_mma<false>, cudaFuncAttributeMaxDynamicSharedMemorySize, SMEM_GEMM3);
    cudaFuncSetAttribute(attn_mma, cudaFuncAttributeMaxDynamicSharedMemorySize, SMEM_ATTN);

    round_x<<<(L_SEQ * DMODEL) / (256 * 4), 256>>>(x, pxr);
    dim3 tb(32, 8);
    dim3 tg(DMODEL / 32, DMODEL / 32, 4);
    transpose_w<<<tg, tb>>>(qw, kw, vw, ow, pwt);

    const float qscale = 0.125f * LOG2E;
    dim3 gqkv(DMODEL / 128, L_SEQ / 128, 3);
    gemm_mma<true><<<gqkv, 256, SMEM_GEMM3>>>(pxr, pwt, pq, pk, pv,
                                              L_SEQ, DMODEL, DMODEL, qscale);

    dim3 ga(L_SEQ / 128, NHEADS);
    attn_mma<<<ga, 256, SMEM_ATTN>>>();

    dim3 gout(DMODEL / 128, L_SEQ / 128, 1);
    gemm_mma<false><<<gout, 256, SMEM_GEMM3>>>(pa, pwt + 3 * (size_t)DMODEL * DMODEL,
                                               out, nullptr, nullptr,
                                               L_SEQ, DMODEL, DMODEL, 1.0f);
}